// round 1
// baseline (speedup 1.0000x reference)
#include <cuda_runtime.h>
#include <math.h>

#define NN 100000
#define DD 128
#define NE 1600000

// Scratch (allocation-free rule: __device__ globals)
__device__ float g_mi[(size_t)NN * DD];
__device__ float g_mo[(size_t)NN * DD];
__device__ float g_h0[(size_t)NN * DD];
__device__ float g_h1[(size_t)NN * DD];

// ---------------------------------------------------------------------------
// Zero mi / mo (must run every launch: graph replays accumulate atomics)
// ---------------------------------------------------------------------------
__global__ void zero2_kernel(float4* __restrict__ a, float4* __restrict__ b, int n4) {
    int i = blockIdx.x * blockDim.x + threadIdx.x;
    if (i < n4) {
        float4 z = make_float4(0.f, 0.f, 0.f, 0.f);
        a[i] = z;
        b[i] = z;
    }
}

// ---------------------------------------------------------------------------
// Edge scatter: one warp per edge.
//   mi[end]   += e * x[start]
//   mo[start] += e * x[end]
// Each lane handles 4 consecutive floats (float4 read, 4 scalar REDs).
// ---------------------------------------------------------------------------
__global__ void scatter_kernel(const float* __restrict__ x,
                               const float* __restrict__ e,
                               const int* __restrict__ ei,
                               float* __restrict__ mi,
                               float* __restrict__ mo) {
    int gw = (blockIdx.x * blockDim.x + threadIdx.x) >> 5;
    int lane = threadIdx.x & 31;
    if (gw >= NE) return;

    int s = ei[gw];
    int t = ei[NE + gw];
    float w = e[gw];

    float4 xs = __ldg((const float4*)(x + (size_t)s * DD) + lane);
    float4 xt = __ldg((const float4*)(x + (size_t)t * DD) + lane);

    float* pmi = mi + (size_t)t * DD + lane * 4;
    atomicAdd(pmi + 0, w * xs.x);
    atomicAdd(pmi + 1, w * xs.y);
    atomicAdd(pmi + 2, w * xs.z);
    atomicAdd(pmi + 3, w * xs.w);

    float* pmo = mo + (size_t)s * DD + lane * 4;
    atomicAdd(pmo + 0, w * xt.x);
    atomicAdd(pmo + 1, w * xt.y);
    atomicAdd(pmo + 2, w * xt.z);
    atomicAdd(pmo + 3, w * xt.w);
}

// ---------------------------------------------------------------------------
// Fused GEMM (sum of up to 3 K=128 input mats) + bias + LayerNorm + tanh.
// Block: 256 threads = 8 warps. Tile: 32 rows x 128 cols.
// Warp ty owns rows [ty*4, ty*4+4); lane tx owns cols [tx*4, tx*4+4).
// -> each output row lives entirely in one warp => LN via warp shuffles.
// ---------------------------------------------------------------------------
__global__ __launch_bounds__(256) void gemm_ln_tanh_kernel(
    const float* __restrict__ A0, const float* __restrict__ A1,
    const float* __restrict__ A2, int nmats,
    const float* __restrict__ Wm,   // [nmats*128, 128] row-major
    const float* __restrict__ bias, // [128]
    const float* __restrict__ gamma,
    const float* __restrict__ beta,
    float* __restrict__ out)        // [NN, 128]
{
    __shared__ float As[32 * 32];    // 32 rows x 32 k
    __shared__ float Bs[32 * 128];   // 32 k x 128 cols

    const int tid = threadIdx.x;
    const int tx = tid & 31;
    const int ty = tid >> 5;
    const int row0 = blockIdx.x * 32;

    float acc[4][4];
#pragma unroll
    for (int r = 0; r < 4; r++)
#pragma unroll
        for (int c = 0; c < 4; c++) acc[r][c] = 0.f;

    const float* Aptrs[3] = {A0, A1, A2};

    for (int m = 0; m < nmats; m++) {
        const float4* A4 = (const float4*)(Aptrs[m]) + (size_t)row0 * 32;
        const float4* W4 = (const float4*)Wm + (size_t)m * 128 * 32;
#pragma unroll
        for (int kc = 0; kc < 4; kc++) {
            __syncthreads();
            // A chunk: 32 rows x 32 k = 256 float4 (1 per thread)
            {
                int ar = tid >> 3;       // row within tile
                int ac = tid & 7;        // float4 col within chunk
                ((float4*)As)[tid] = A4[ar * 32 + kc * 8 + ac];
            }
            // B chunk: 32 k x 128 cols = 1024 float4 (4 per thread)
#pragma unroll
            for (int i = 0; i < 4; i++) {
                int idx = tid + i * 256;
                ((float4*)Bs)[idx] = W4[kc * 32 * 32 + idx];
            }
            __syncthreads();

#pragma unroll
            for (int kk = 0; kk < 32; kk++) {
                float4 bv = ((const float4*)Bs)[kk * 32 + tx];
#pragma unroll
                for (int r = 0; r < 4; r++) {
                    float a = As[(ty * 4 + r) * 32 + kk];
                    acc[r][0] = fmaf(a, bv.x, acc[r][0]);
                    acc[r][1] = fmaf(a, bv.y, acc[r][1]);
                    acc[r][2] = fmaf(a, bv.z, acc[r][2]);
                    acc[r][3] = fmaf(a, bv.w, acc[r][3]);
                }
            }
        }
    }

    // Epilogue: bias + LN + tanh, one warp owns each row fully.
    const int colb = tx * 4;
    float bb0 = bias[colb], bb1 = bias[colb + 1], bb2 = bias[colb + 2], bb3 = bias[colb + 3];
    float gg0 = gamma[colb], gg1 = gamma[colb + 1], gg2 = gamma[colb + 2], gg3 = gamma[colb + 3];
    float ee0 = beta[colb], ee1 = beta[colb + 1], ee2 = beta[colb + 2], ee3 = beta[colb + 3];

#pragma unroll
    for (int r = 0; r < 4; r++) {
        float v0 = acc[r][0] + bb0;
        float v1 = acc[r][1] + bb1;
        float v2 = acc[r][2] + bb2;
        float v3 = acc[r][3] + bb3;
        float s = v0 + v1 + v2 + v3;
        float q = v0 * v0 + v1 * v1 + v2 * v2 + v3 * v3;
#pragma unroll
        for (int o = 16; o > 0; o >>= 1) {
            s += __shfl_xor_sync(0xFFFFFFFFu, s, o);
            q += __shfl_xor_sync(0xFFFFFFFFu, q, o);
        }
        float mean = s * (1.f / 128.f);
        float var = q * (1.f / 128.f) - mean * mean;
        float rstd = rsqrtf(var + 1e-5f);

        float4 o4;
        o4.x = tanhf((v0 - mean) * rstd * gg0 + ee0);
        o4.y = tanhf((v1 - mean) * rstd * gg1 + ee1);
        o4.z = tanhf((v2 - mean) * rstd * gg2 + ee2);
        o4.w = tanhf((v3 - mean) * rstd * gg3 + ee3);

        int row = row0 + ty * 4 + r;
        ((float4*)(out + (size_t)row * DD))[tx] = o4;
    }
}

// ---------------------------------------------------------------------------
extern "C" void kernel_launch(void* const* d_in, const int* in_sizes, int n_in,
                              void* d_out, int out_size) {
    const float* x   = (const float*)d_in[0];
    const float* e   = (const float*)d_in[1];
    const int*   ei  = (const int*)d_in[2];
    const float* W0  = (const float*)d_in[3];
    const float* b0  = (const float*)d_in[4];
    const float* g0  = (const float*)d_in[5];
    const float* be0 = (const float*)d_in[6];
    const float* W   = (const float*)d_in[7];
    const float* b   = (const float*)d_in[8];
    const float* g   = (const float*)d_in[9];
    const float* be  = (const float*)d_in[10];
    float* out = (float*)d_out;

    float *mi, *mo, *h0, *h1;
    cudaGetSymbolAddress((void**)&mi, g_mi);
    cudaGetSymbolAddress((void**)&mo, g_mo);
    cudaGetSymbolAddress((void**)&h0, g_h0);
    cudaGetSymbolAddress((void**)&h1, g_h1);

    // 1) zero accumulators
    {
        int n4 = NN * DD / 4;
        int blocks = (n4 + 255) / 256;
        zero2_kernel<<<blocks, 256>>>((float4*)mi, (float4*)mo, n4);
    }

    // 2) edge scatter (one warp per edge)
    {
        long long threads = (long long)NE * 32;
        int blocks = (int)((threads + 255) / 256);
        scatter_kernel<<<blocks, 256>>>(x, e, ei, mi, mo);
    }

    const int gblocks = NN / 32;  // 3125

    // 3) GEMM0: [mi|mo|x] @ W0 + LN + tanh -> h0
    gemm_ln_tanh_kernel<<<gblocks, 256>>>(mi, mo, x, 3, W0, b0, g0, be0, h0);

    // 4) three layers
    gemm_ln_tanh_kernel<<<gblocks, 256>>>(h0, nullptr, nullptr, 1,
                                          W, b, g, be, h1);
    gemm_ln_tanh_kernel<<<gblocks, 256>>>(h1, nullptr, nullptr, 1,
                                          W + 128 * 128, b + 128, g + 128, be + 128, h0);
    gemm_ln_tanh_kernel<<<gblocks, 256>>>(h0, nullptr, nullptr, 1,
                                          W + 2 * 128 * 128, b + 2 * 128, g + 2 * 128, be + 2 * 128, out);
}

// round 2
// speedup vs baseline: 1.6335x; 1.6335x over previous
#include <cuda_runtime.h>
#include <math.h>

#define NN 100000
#define DD 128
#define NE 1600000

// Scratch (allocation-free rule: __device__ globals)
__device__ float g_mi[(size_t)NN * DD];
__device__ float g_mo[(size_t)NN * DD];
__device__ float g_h0[(size_t)NN * DD];
__device__ float g_h1[(size_t)NN * DD];

__device__ int  g_cnt_in[NN];
__device__ int  g_cnt_out[NN];
__device__ int  g_off_in[NN + 1];
__device__ int  g_off_out[NN + 1];
__device__ int  g_cur_in[NN];
__device__ int  g_cur_out[NN];
__device__ int2 g_lst_in[NE];    // {src, weight-bits}, keyed by dst
__device__ int2 g_lst_out[NE];   // {dst, weight-bits}, keyed by src

// ---------------------------------------------------------------------------
// Histogram of edge endpoints
// ---------------------------------------------------------------------------
__global__ void hist_kernel(const int* __restrict__ ei,
                            int* __restrict__ cin, int* __restrict__ cout) {
    int i = blockIdx.x * blockDim.x + threadIdx.x;
    if (i >= NE) return;
    int s = ei[i];
    int t = ei[NE + i];
    atomicAdd(&cin[t], 1);
    atomicAdd(&cout[s], 1);
}

// ---------------------------------------------------------------------------
// Exclusive scan of a 100k counter array. One 1024-thread block per array.
// blockIdx.x = 0 -> in arrays, 1 -> out arrays.
// ---------------------------------------------------------------------------
#define SCAN_CHUNK 98   // 1024 * 98 >= 100000
__global__ __launch_bounds__(1024) void scan_kernel(
    const int* __restrict__ cin, int* __restrict__ offin, int* __restrict__ curin,
    const int* __restrict__ cout, int* __restrict__ offout, int* __restrict__ curout) {
    const int* cnt = blockIdx.x == 0 ? cin : cout;
    int* off = blockIdx.x == 0 ? offin : offout;
    int* cur = blockIdx.x == 0 ? curin : curout;

    __shared__ int ssum[1024];
    int t = threadIdx.x;
    int base = t * SCAN_CHUNK;

    int s = 0;
#pragma unroll 4
    for (int k = 0; k < SCAN_CHUNK; k++) {
        int idx = base + k;
        if (idx < NN) s += cnt[idx];
    }
    ssum[t] = s;
    __syncthreads();

    // inclusive Hillis-Steele scan over 1024 partials
    for (int o = 1; o < 1024; o <<= 1) {
        int v = (t >= o) ? ssum[t - o] : 0;
        __syncthreads();
        ssum[t] += v;
        __syncthreads();
    }

    int run = (t > 0) ? ssum[t - 1] : 0;
#pragma unroll 4
    for (int k = 0; k < SCAN_CHUNK; k++) {
        int idx = base + k;
        if (idx < NN) {
            int c = cnt[idx];
            off[idx] = run;
            cur[idx] = run;
            run += c;
        }
    }
    if (t == 0) off[NN] = ssum[1023];
}

// ---------------------------------------------------------------------------
// Fill CSR edge lists (atomic cursors)
// ---------------------------------------------------------------------------
__global__ void fill_kernel(const int* __restrict__ ei, const float* __restrict__ e,
                            int* __restrict__ curin, int* __restrict__ curout,
                            int2* __restrict__ lin, int2* __restrict__ lout) {
    int i = blockIdx.x * blockDim.x + threadIdx.x;
    if (i >= NE) return;
    int s = ei[i];
    int t = ei[NE + i];
    int wb = __float_as_int(e[i]);
    int p1 = atomicAdd(&curin[t], 1);
    lin[p1] = make_int2(s, wb);
    int p2 = atomicAdd(&curout[s], 1);
    lout[p2] = make_int2(t, wb);
}

// ---------------------------------------------------------------------------
// Gather: one warp per node. Lane owns 4 consecutive columns.
//   out[n] = sum_j w_j * x[nbr_j]
// ---------------------------------------------------------------------------
__global__ __launch_bounds__(256) void gather_kernel(
    const float* __restrict__ x,
    const int* __restrict__ off,
    const int2* __restrict__ lst,
    float* __restrict__ out) {
    int w = (blockIdx.x * blockDim.x + threadIdx.x) >> 5;
    int lane = threadIdx.x & 31;
    if (w >= NN) return;

    int beg = off[w];
    int end = off[w + 1];

    float4 acc = make_float4(0.f, 0.f, 0.f, 0.f);

    int j = beg;
    // 2x unroll for MLP
    for (; j + 2 <= end; j += 2) {
        int2 p0 = __ldg(&lst[j]);
        int2 p1 = __ldg(&lst[j + 1]);
        float4 v0 = __ldg((const float4*)(x + (size_t)p0.x * DD) + lane);
        float4 v1 = __ldg((const float4*)(x + (size_t)p1.x * DD) + lane);
        float w0 = __int_as_float(p0.y);
        float w1 = __int_as_float(p1.y);
        acc.x = fmaf(w0, v0.x, acc.x); acc.y = fmaf(w0, v0.y, acc.y);
        acc.z = fmaf(w0, v0.z, acc.z); acc.w = fmaf(w0, v0.w, acc.w);
        acc.x = fmaf(w1, v1.x, acc.x); acc.y = fmaf(w1, v1.y, acc.y);
        acc.z = fmaf(w1, v1.z, acc.z); acc.w = fmaf(w1, v1.w, acc.w);
    }
    if (j < end) {
        int2 p0 = __ldg(&lst[j]);
        float4 v0 = __ldg((const float4*)(x + (size_t)p0.x * DD) + lane);
        float w0 = __int_as_float(p0.y);
        acc.x = fmaf(w0, v0.x, acc.x); acc.y = fmaf(w0, v0.y, acc.y);
        acc.z = fmaf(w0, v0.z, acc.z); acc.w = fmaf(w0, v0.w, acc.w);
    }

    ((float4*)(out + (size_t)w * DD))[lane] = acc;
}

// ---------------------------------------------------------------------------
// Fused GEMM (sum of up to 3 K=128 input mats) + bias + LayerNorm + tanh.
// Block: 256 threads = 8 warps. Tile: 32 rows x 128 cols.
// ---------------------------------------------------------------------------
__global__ __launch_bounds__(256) void gemm_ln_tanh_kernel(
    const float* __restrict__ A0, const float* __restrict__ A1,
    const float* __restrict__ A2, int nmats,
    const float* __restrict__ Wm,   // [nmats*128, 128] row-major
    const float* __restrict__ bias,
    const float* __restrict__ gamma,
    const float* __restrict__ beta,
    float* __restrict__ out)
{
    __shared__ float As[32 * 32];
    __shared__ float Bs[32 * 128];

    const int tid = threadIdx.x;
    const int tx = tid & 31;
    const int ty = tid >> 5;
    const int row0 = blockIdx.x * 32;

    float acc[4][4];
#pragma unroll
    for (int r = 0; r < 4; r++)
#pragma unroll
        for (int c = 0; c < 4; c++) acc[r][c] = 0.f;

    const float* Aptrs[3] = {A0, A1, A2};

    for (int m = 0; m < nmats; m++) {
        const float4* A4 = (const float4*)(Aptrs[m]) + (size_t)row0 * 32;
        const float4* W4 = (const float4*)Wm + (size_t)m * 128 * 32;
#pragma unroll
        for (int kc = 0; kc < 4; kc++) {
            __syncthreads();
            {
                int ar = tid >> 3;
                int ac = tid & 7;
                ((float4*)As)[tid] = A4[ar * 32 + kc * 8 + ac];
            }
#pragma unroll
            for (int i = 0; i < 4; i++) {
                int idx = tid + i * 256;
                ((float4*)Bs)[idx] = W4[kc * 32 * 32 + idx];
            }
            __syncthreads();

#pragma unroll
            for (int kk = 0; kk < 32; kk++) {
                float4 bv = ((const float4*)Bs)[kk * 32 + tx];
#pragma unroll
                for (int r = 0; r < 4; r++) {
                    float a = As[(ty * 4 + r) * 32 + kk];
                    acc[r][0] = fmaf(a, bv.x, acc[r][0]);
                    acc[r][1] = fmaf(a, bv.y, acc[r][1]);
                    acc[r][2] = fmaf(a, bv.z, acc[r][2]);
                    acc[r][3] = fmaf(a, bv.w, acc[r][3]);
                }
            }
        }
    }

    const int colb = tx * 4;
    float bb0 = bias[colb], bb1 = bias[colb + 1], bb2 = bias[colb + 2], bb3 = bias[colb + 3];
    float gg0 = gamma[colb], gg1 = gamma[colb + 1], gg2 = gamma[colb + 2], gg3 = gamma[colb + 3];
    float ee0 = beta[colb], ee1 = beta[colb + 1], ee2 = beta[colb + 2], ee3 = beta[colb + 3];

#pragma unroll
    for (int r = 0; r < 4; r++) {
        float v0 = acc[r][0] + bb0;
        float v1 = acc[r][1] + bb1;
        float v2 = acc[r][2] + bb2;
        float v3 = acc[r][3] + bb3;
        float s = v0 + v1 + v2 + v3;
        float q = v0 * v0 + v1 * v1 + v2 * v2 + v3 * v3;
#pragma unroll
        for (int o = 16; o > 0; o >>= 1) {
            s += __shfl_xor_sync(0xFFFFFFFFu, s, o);
            q += __shfl_xor_sync(0xFFFFFFFFu, q, o);
        }
        float mean = s * (1.f / 128.f);
        float var = q * (1.f / 128.f) - mean * mean;
        float rstd = rsqrtf(var + 1e-5f);

        float4 o4;
        o4.x = tanhf((v0 - mean) * rstd * gg0 + ee0);
        o4.y = tanhf((v1 - mean) * rstd * gg1 + ee1);
        o4.z = tanhf((v2 - mean) * rstd * gg2 + ee2);
        o4.w = tanhf((v3 - mean) * rstd * gg3 + ee3);

        int row = row0 + ty * 4 + r;
        ((float4*)(out + (size_t)row * DD))[tx] = o4;
    }
}

// ---------------------------------------------------------------------------
extern "C" void kernel_launch(void* const* d_in, const int* in_sizes, int n_in,
                              void* d_out, int out_size) {
    const float* x   = (const float*)d_in[0];
    const float* e   = (const float*)d_in[1];
    const int*   ei  = (const int*)d_in[2];
    const float* W0  = (const float*)d_in[3];
    const float* b0  = (const float*)d_in[4];
    const float* g0  = (const float*)d_in[5];
    const float* be0 = (const float*)d_in[6];
    const float* W   = (const float*)d_in[7];
    const float* b   = (const float*)d_in[8];
    const float* g   = (const float*)d_in[9];
    const float* be  = (const float*)d_in[10];
    float* out = (float*)d_out;

    float *mi, *mo, *h0, *h1;
    int *cin, *cout_, *offin, *offout, *curin, *curout;
    int2 *lin, *lout;
    cudaGetSymbolAddress((void**)&mi, g_mi);
    cudaGetSymbolAddress((void**)&mo, g_mo);
    cudaGetSymbolAddress((void**)&h0, g_h0);
    cudaGetSymbolAddress((void**)&h1, g_h1);
    cudaGetSymbolAddress((void**)&cin, g_cnt_in);
    cudaGetSymbolAddress((void**)&cout_, g_cnt_out);
    cudaGetSymbolAddress((void**)&offin, g_off_in);
    cudaGetSymbolAddress((void**)&offout, g_off_out);
    cudaGetSymbolAddress((void**)&curin, g_cur_in);
    cudaGetSymbolAddress((void**)&curout, g_cur_out);
    cudaGetSymbolAddress((void**)&lin, g_lst_in);
    cudaGetSymbolAddress((void**)&lout, g_lst_out);

    // 1) zero counters
    cudaMemsetAsync(cin, 0, NN * sizeof(int));
    cudaMemsetAsync(cout_, 0, NN * sizeof(int));

    // 2) histogram
    hist_kernel<<<(NE + 255) / 256, 256>>>(ei, cin, cout_);

    // 3) scan (block 0 -> in, block 1 -> out)
    scan_kernel<<<2, 1024>>>(cin, offin, curin, cout_, offout, curout);

    // 4) fill CSR lists
    fill_kernel<<<(NE + 255) / 256, 256>>>(ei, e, curin, curout, lin, lout);

    // 5) gather (no atomics)
    {
        int blocks = (NN * 32 + 255) / 256;
        gather_kernel<<<blocks, 256>>>(x, offin, lin, mi);
        gather_kernel<<<blocks, 256>>>(x, offout, lout, mo);
    }

    const int gblocks = NN / 32;  // 3125

    // 6) GEMM0: [mi|mo|x] @ W0 + LN + tanh -> h0
    gemm_ln_tanh_kernel<<<gblocks, 256>>>(mi, mo, x, 3, W0, b0, g0, be0, h0);

    // 7) three layers
    gemm_ln_tanh_kernel<<<gblocks, 256>>>(h0, nullptr, nullptr, 1,
                                          W, b, g, be, h1);
    gemm_ln_tanh_kernel<<<gblocks, 256>>>(h1, nullptr, nullptr, 1,
                                          W + 128 * 128, b + 128, g + 128, be + 128, h0);
    gemm_ln_tanh_kernel<<<gblocks, 256>>>(h0, nullptr, nullptr, 1,
                                          W + 2 * 128 * 128, b + 2 * 128, g + 2 * 128, be + 2 * 128, out);
}

// round 3
// speedup vs baseline: 2.2816x; 1.3967x over previous
#include <cuda_runtime.h>
#include <math.h>
#include <stdint.h>

#define NN 100000
#define DD 128
#define NE 1600000

// Scratch (allocation-free rule: __device__ globals)
__device__ float g_mi[(size_t)NN * DD];
__device__ float g_mo[(size_t)NN * DD];
__device__ float g_h0[(size_t)NN * DD];
__device__ float g_h1[(size_t)NN * DD];

__device__ int  g_cnt_in[NN];
__device__ int  g_cnt_out[NN];
__device__ int  g_off_in[NN + 1];
__device__ int  g_off_out[NN + 1];
__device__ int  g_cur_in[NN];
__device__ int  g_cur_out[NN];
__device__ int2 g_lst_in[NE];    // {src, weight-bits}, keyed by dst
__device__ int2 g_lst_out[NE];   // {dst, weight-bits}, keyed by src

// ---------------------------------------------------------------------------
// Histogram of edge endpoints
// ---------------------------------------------------------------------------
__global__ void hist_kernel(const int* __restrict__ ei,
                            int* __restrict__ cin, int* __restrict__ cout) {
    int i = blockIdx.x * blockDim.x + threadIdx.x;
    if (i >= NE) return;
    int s = ei[i];
    int t = ei[NE + i];
    atomicAdd(&cin[t], 1);
    atomicAdd(&cout[s], 1);
}

// ---------------------------------------------------------------------------
// Exclusive scan of a 100k counter array. One 1024-thread block per array.
// ---------------------------------------------------------------------------
#define SCAN_CHUNK 98
__global__ __launch_bounds__(1024) void scan_kernel(
    const int* __restrict__ cin, int* __restrict__ offin, int* __restrict__ curin,
    const int* __restrict__ cout, int* __restrict__ offout, int* __restrict__ curout) {
    const int* cnt = blockIdx.x == 0 ? cin : cout;
    int* off = blockIdx.x == 0 ? offin : offout;
    int* cur = blockIdx.x == 0 ? curin : curout;

    __shared__ int ssum[1024];
    int t = threadIdx.x;
    int base = t * SCAN_CHUNK;

    int s = 0;
#pragma unroll 4
    for (int k = 0; k < SCAN_CHUNK; k++) {
        int idx = base + k;
        if (idx < NN) s += cnt[idx];
    }
    ssum[t] = s;
    __syncthreads();

    for (int o = 1; o < 1024; o <<= 1) {
        int v = (t >= o) ? ssum[t - o] : 0;
        __syncthreads();
        ssum[t] += v;
        __syncthreads();
    }

    int run = (t > 0) ? ssum[t - 1] : 0;
#pragma unroll 4
    for (int k = 0; k < SCAN_CHUNK; k++) {
        int idx = base + k;
        if (idx < NN) {
            int c = cnt[idx];
            off[idx] = run;
            cur[idx] = run;
            run += c;
        }
    }
    if (t == 0) off[NN] = ssum[1023];
}

// ---------------------------------------------------------------------------
// Fill CSR edge lists (atomic cursors)
// ---------------------------------------------------------------------------
__global__ void fill_kernel(const int* __restrict__ ei, const float* __restrict__ e,
                            int* __restrict__ curin, int* __restrict__ curout,
                            int2* __restrict__ lin, int2* __restrict__ lout) {
    int i = blockIdx.x * blockDim.x + threadIdx.x;
    if (i >= NE) return;
    int s = ei[i];
    int t = ei[NE + i];
    int wb = __float_as_int(e[i]);
    int p1 = atomicAdd(&curin[t], 1);
    lin[p1] = make_int2(s, wb);
    int p2 = atomicAdd(&curout[s], 1);
    lout[p2] = make_int2(t, wb);
}

// ---------------------------------------------------------------------------
// Gather: one warp per node, 4x unrolled for MLP.
// ---------------------------------------------------------------------------
__global__ __launch_bounds__(256) void gather_kernel(
    const float* __restrict__ x,
    const int* __restrict__ off,
    const int2* __restrict__ lst,
    float* __restrict__ out) {
    int w = (blockIdx.x * blockDim.x + threadIdx.x) >> 5;
    int lane = threadIdx.x & 31;
    if (w >= NN) return;

    int beg = off[w];
    int end = off[w + 1];

    float4 acc = make_float4(0.f, 0.f, 0.f, 0.f);

    int j = beg;
    for (; j + 4 <= end; j += 4) {
        int2 p0 = __ldg(&lst[j]);
        int2 p1 = __ldg(&lst[j + 1]);
        int2 p2 = __ldg(&lst[j + 2]);
        int2 p3 = __ldg(&lst[j + 3]);
        float4 v0 = __ldg((const float4*)(x + (size_t)p0.x * DD) + lane);
        float4 v1 = __ldg((const float4*)(x + (size_t)p1.x * DD) + lane);
        float4 v2 = __ldg((const float4*)(x + (size_t)p2.x * DD) + lane);
        float4 v3 = __ldg((const float4*)(x + (size_t)p3.x * DD) + lane);
        float w0 = __int_as_float(p0.y), w1 = __int_as_float(p1.y);
        float w2 = __int_as_float(p2.y), w3 = __int_as_float(p3.y);
        acc.x = fmaf(w0, v0.x, acc.x); acc.y = fmaf(w0, v0.y, acc.y);
        acc.z = fmaf(w0, v0.z, acc.z); acc.w = fmaf(w0, v0.w, acc.w);
        acc.x = fmaf(w1, v1.x, acc.x); acc.y = fmaf(w1, v1.y, acc.y);
        acc.z = fmaf(w1, v1.z, acc.z); acc.w = fmaf(w1, v1.w, acc.w);
        acc.x = fmaf(w2, v2.x, acc.x); acc.y = fmaf(w2, v2.y, acc.y);
        acc.z = fmaf(w2, v2.z, acc.z); acc.w = fmaf(w2, v2.w, acc.w);
        acc.x = fmaf(w3, v3.x, acc.x); acc.y = fmaf(w3, v3.y, acc.y);
        acc.z = fmaf(w3, v3.z, acc.z); acc.w = fmaf(w3, v3.w, acc.w);
    }
    for (; j < end; j++) {
        int2 p0 = __ldg(&lst[j]);
        float4 v0 = __ldg((const float4*)(x + (size_t)p0.x * DD) + lane);
        float w0 = __int_as_float(p0.y);
        acc.x = fmaf(w0, v0.x, acc.x); acc.y = fmaf(w0, v0.y, acc.y);
        acc.z = fmaf(w0, v0.z, acc.z); acc.w = fmaf(w0, v0.w, acc.w);
    }

    ((float4*)(out + (size_t)w * DD))[lane] = acc;
}

// ---------------------------------------------------------------------------
// tf32 tensor-core GEMM + bias + LayerNorm + tanh.
// Block: 256 threads = 8 warps. Tile: 128 rows x 128 cols.
// Warp w owns rows [w*16, w*16+16) fully -> LN via quad shuffles.
// mma.sync.m16n8k8.row.col tf32.
// ---------------------------------------------------------------------------
__device__ __forceinline__ uint32_t f2tf32(float v) {
    uint32_t r;
    asm("cvt.rna.tf32.f32 %0, %1;" : "=r"(r) : "f"(v));
    return r;
}

__global__ __launch_bounds__(256, 2) void gemm_ln_tanh_mma(
    const float* __restrict__ A0, const float* __restrict__ A1,
    const float* __restrict__ A2, int nmats,
    const float* __restrict__ Wm,   // [nmats*128, 128] row-major
    const float* __restrict__ bias,
    const float* __restrict__ gamma,
    const float* __restrict__ beta,
    float* __restrict__ out)
{
    __shared__ uint32_t As[128][36];   // 128 rows x 32 k (pad 36: conflict-free frag loads)
    __shared__ uint32_t Ws[32][132];   // 32 k x 128 n (pad 132)

    const int tid = threadIdx.x;
    const int lane = tid & 31;
    const int wid = tid >> 5;
    const int g = lane >> 2;     // 0..7
    const int t4 = lane & 3;     // 0..3
    const int row0 = blockIdx.x * 128;
    const int wrow = wid * 16;

    float c[16][4];
#pragma unroll
    for (int j = 0; j < 16; j++)
#pragma unroll
        for (int q = 0; q < 4; q++) c[j][q] = 0.f;

    const float* Ap[3] = {A0, A1, A2};

    for (int m = 0; m < nmats; m++) {
        const float4* A4 = (const float4*)(Ap[m]);
        for (int kc = 0; kc < 4; kc++) {
            __syncthreads();
            // Load A tile: 128 rows x 32 k = 1024 float4, 4 per thread
#pragma unroll
            for (int i = 0; i < 4; i++) {
                int idx = tid + i * 256;
                int r = idx >> 3;
                int c4 = idx & 7;
                int grow = row0 + r;
                if (grow >= NN) grow = 0;
                float4 v = __ldg(&A4[(size_t)grow * 32 + kc * 8 + c4]);
                As[r][c4 * 4 + 0] = f2tf32(v.x);
                As[r][c4 * 4 + 1] = f2tf32(v.y);
                As[r][c4 * 4 + 2] = f2tf32(v.z);
                As[r][c4 * 4 + 3] = f2tf32(v.w);
            }
            // Load W chunk: 32 k x 128 n = 1024 float4, 4 per thread
            const float4* W4 = (const float4*)Wm + (size_t)(m * 128 + kc * 32) * 32;
#pragma unroll
            for (int i = 0; i < 4; i++) {
                int idx = tid + i * 256;
                int k = idx >> 5;
                int n4 = idx & 31;
                float4 v = __ldg(&W4[k * 32 + n4]);
                Ws[k][n4 * 4 + 0] = f2tf32(v.x);
                Ws[k][n4 * 4 + 1] = f2tf32(v.y);
                Ws[k][n4 * 4 + 2] = f2tf32(v.z);
                Ws[k][n4 * 4 + 3] = f2tf32(v.w);
            }
            __syncthreads();

#pragma unroll
            for (int ks = 0; ks < 4; ks++) {
                uint32_t a0 = As[wrow + g][ks * 8 + t4];
                uint32_t a1 = As[wrow + g + 8][ks * 8 + t4];
                uint32_t a2 = As[wrow + g][ks * 8 + t4 + 4];
                uint32_t a3 = As[wrow + g + 8][ks * 8 + t4 + 4];
#pragma unroll
                for (int j = 0; j < 16; j++) {
                    uint32_t b0 = Ws[ks * 8 + t4][j * 8 + g];
                    uint32_t b1 = Ws[ks * 8 + t4 + 4][j * 8 + g];
                    asm volatile(
                        "mma.sync.aligned.m16n8k8.row.col.f32.tf32.tf32.f32 "
                        "{%0,%1,%2,%3}, {%4,%5,%6,%7}, {%8,%9}, {%0,%1,%2,%3};"
                        : "+f"(c[j][0]), "+f"(c[j][1]), "+f"(c[j][2]), "+f"(c[j][3])
                        : "r"(a0), "r"(a1), "r"(a2), "r"(a3), "r"(b0), "r"(b1));
                }
            }
        }
    }

    // Epilogue: bias + LN + tanh.
    // Lane owns cols {j*8 + 2*t4, j*8 + 2*t4 + 1} for rows r1 = row0+wrow+g and r2 = r1+8.
    float s1 = 0.f, q1 = 0.f, s2 = 0.f, q2 = 0.f;
#pragma unroll
    for (int j = 0; j < 16; j++) {
        int col = j * 8 + 2 * t4;
        float2 bb = *(const float2*)(bias + col);
        c[j][0] += bb.x; c[j][1] += bb.y;
        c[j][2] += bb.x; c[j][3] += bb.y;
        s1 += c[j][0] + c[j][1];
        q1 += c[j][0] * c[j][0] + c[j][1] * c[j][1];
        s2 += c[j][2] + c[j][3];
        q2 += c[j][2] * c[j][2] + c[j][3] * c[j][3];
    }
    // Reduce across quad (lanes g*4 .. g*4+3)
#pragma unroll
    for (int o = 1; o <= 2; o <<= 1) {
        s1 += __shfl_xor_sync(0xFFFFFFFFu, s1, o);
        q1 += __shfl_xor_sync(0xFFFFFFFFu, q1, o);
        s2 += __shfl_xor_sync(0xFFFFFFFFu, s2, o);
        q2 += __shfl_xor_sync(0xFFFFFFFFu, q2, o);
    }
    float m1 = s1 * (1.f / 128.f);
    float var1 = q1 * (1.f / 128.f) - m1 * m1;
    float r1 = rsqrtf(var1 + 1e-5f);
    float m2 = s2 * (1.f / 128.f);
    float var2 = q2 * (1.f / 128.f) - m2 * m2;
    float r2 = rsqrtf(var2 + 1e-5f);

    int grow1 = row0 + wrow + g;
    int grow2 = grow1 + 8;
#pragma unroll
    for (int j = 0; j < 16; j++) {
        int col = j * 8 + 2 * t4;
        float2 gg = *(const float2*)(gamma + col);
        float2 ee = *(const float2*)(beta + col);
        if (grow1 < NN) {
            float2 o1;
            o1.x = tanhf((c[j][0] - m1) * r1 * gg.x + ee.x);
            o1.y = tanhf((c[j][1] - m1) * r1 * gg.y + ee.y);
            *(float2*)(out + (size_t)grow1 * DD + col) = o1;
        }
        if (grow2 < NN) {
            float2 o2;
            o2.x = tanhf((c[j][2] - m2) * r2 * gg.x + ee.x);
            o2.y = tanhf((c[j][3] - m2) * r2 * gg.y + ee.y);
            *(float2*)(out + (size_t)grow2 * DD + col) = o2;
        }
    }
}

// ---------------------------------------------------------------------------
extern "C" void kernel_launch(void* const* d_in, const int* in_sizes, int n_in,
                              void* d_out, int out_size) {
    const float* x   = (const float*)d_in[0];
    const float* e   = (const float*)d_in[1];
    const int*   ei  = (const int*)d_in[2];
    const float* W0  = (const float*)d_in[3];
    const float* b0  = (const float*)d_in[4];
    const float* g0  = (const float*)d_in[5];
    const float* be0 = (const float*)d_in[6];
    const float* W   = (const float*)d_in[7];
    const float* b   = (const float*)d_in[8];
    const float* g   = (const float*)d_in[9];
    const float* be  = (const float*)d_in[10];
    float* out = (float*)d_out;

    float *mi, *mo, *h0, *h1;
    int *cin, *cout_, *offin, *offout, *curin, *curout;
    int2 *lin, *lout;
    cudaGetSymbolAddress((void**)&mi, g_mi);
    cudaGetSymbolAddress((void**)&mo, g_mo);
    cudaGetSymbolAddress((void**)&h0, g_h0);
    cudaGetSymbolAddress((void**)&h1, g_h1);
    cudaGetSymbolAddress((void**)&cin, g_cnt_in);
    cudaGetSymbolAddress((void**)&cout_, g_cnt_out);
    cudaGetSymbolAddress((void**)&offin, g_off_in);
    cudaGetSymbolAddress((void**)&offout, g_off_out);
    cudaGetSymbolAddress((void**)&curin, g_cur_in);
    cudaGetSymbolAddress((void**)&curout, g_cur_out);
    cudaGetSymbolAddress((void**)&lin, g_lst_in);
    cudaGetSymbolAddress((void**)&lout, g_lst_out);

    cudaMemsetAsync(cin, 0, NN * sizeof(int));
    cudaMemsetAsync(cout_, 0, NN * sizeof(int));

    hist_kernel<<<(NE + 255) / 256, 256>>>(ei, cin, cout_);
    scan_kernel<<<2, 1024>>>(cin, offin, curin, cout_, offout, curout);
    fill_kernel<<<(NE + 255) / 256, 256>>>(ei, e, curin, curout, lin, lout);

    {
        int blocks = (NN * 32 + 255) / 256;
        gather_kernel<<<blocks, 256>>>(x, offin, lin, mi);
        gather_kernel<<<blocks, 256>>>(x, offout, lout, mo);
    }

    const int gblocks = (NN + 127) / 128;  // 782

    gemm_ln_tanh_mma<<<gblocks, 256>>>(mi, mo, x, 3, W0, b0, g0, be0, h0);
    gemm_ln_tanh_mma<<<gblocks, 256>>>(h0, nullptr, nullptr, 1,
                                       W, b, g, be, h1);
    gemm_ln_tanh_mma<<<gblocks, 256>>>(h1, nullptr, nullptr, 1,
                                       W + 128 * 128, b + 128, g + 128, be + 128, h0);
    gemm_ln_tanh_mma<<<gblocks, 256>>>(h0, nullptr, nullptr, 1,
                                       W + 2 * 128 * 128, b + 2 * 128, g + 2 * 128, be + 2 * 128, out);
}